// round 4
// baseline (speedup 1.0000x reference)
#include <cuda_runtime.h>
#include <cuda_bf16.h>
#include <math.h>

#define NNODE 50000
#define NEDGE 800000
#define ETOT  (NEDGE + NNODE)   // 850000 with self loops
#define FDIM  128               // HEADS*HID == HEADS*OUT == 128
#define HEADS 8
#define CH    16

// ---------------- scratch (allocation-free: one big __device__ array) -------
#define OFF_XL1   0ull
#define OFF_XR1   (OFF_XL1 + (size_t)NNODE * FDIM)
#define OFF_EX1   (OFF_XR1 + (size_t)NNODE * FDIM)
#define OFF_DEN1  (OFF_EX1 + (size_t)ETOT * HEADS)
#define OFF_ACC1  (OFF_DEN1 + (size_t)NNODE * HEADS)
#define OFF_H1    (OFF_ACC1 + (size_t)NNODE * FDIM)
#define OFF_XL2   (OFF_H1 + (size_t)NNODE * FDIM)
#define OFF_XR2   (OFF_XL2 + (size_t)NNODE * FDIM)
#define OFF_EX2   (OFF_XR2 + (size_t)NNODE * FDIM)
#define OFF_DEN2  (OFF_EX2 + (size_t)ETOT * HEADS)
#define OFF_OUT2  (OFF_DEN2 + (size_t)NNODE * HEADS)
#define SCRATCH_TOTAL (OFF_OUT2 + (size_t)NNODE * FDIM)

__device__ float g_scratch[SCRATCH_TOTAL];

// ---------------- zero the accumulators -------------------------------------
__global__ void zero_scratch_kernel() {
    size_t i = (size_t)blockIdx.x * blockDim.x + threadIdx.x;
    size_t stride = (size_t)gridDim.x * blockDim.x;
    float* acc1 = g_scratch + OFF_ACC1;
    float* out2 = g_scratch + OFF_OUT2;
    float* den1 = g_scratch + OFF_DEN1;
    float* den2 = g_scratch + OFF_DEN2;
    for (size_t k = i; k < (size_t)NNODE * FDIM; k += stride) { acc1[k] = 0.f; out2[k] = 0.f; }
    for (size_t k = i; k < (size_t)NNODE * HEADS; k += stride) { den1[k] = 0.f; den2[k] = 0.f; }
}

// ---------------- GEMM: Y[M,128] = X[M,128] @ W[128,128]^T + b --------------
__global__ void gemm128_kernel(const float* __restrict__ X,
                               const float* __restrict__ W,
                               const float* __restrict__ b,
                               float* __restrict__ Y, int M) {
    extern __shared__ float smem[];
    float* sW = smem;             // 128*128 transposed
    float* sX = smem + 128 * 128; // 8*128
    int t = threadIdx.x;          // 0..127

    const float4* wrow = (const float4*)(W + (size_t)t * 128);
#pragma unroll
    for (int i = 0; i < 32; i++) {
        float4 v = wrow[i];
        int k = i * 4;
        sW[(k + 0) * 128 + t] = v.x;
        sW[(k + 1) * 128 + t] = v.y;
        sW[(k + 2) * 128 + t] = v.z;
        sW[(k + 3) * 128 + t] = v.w;
    }
    int row0 = blockIdx.x * 8;
    const float4* xp = (const float4*)(X + (size_t)row0 * 128);
    float4* sx4 = (float4*)sX;
#pragma unroll
    for (int i = 0; i < 2; i++) sx4[t + i * 128] = xp[t + i * 128];
    __syncthreads();

    float bb = b[t];
    float acc[8];
#pragma unroll
    for (int r = 0; r < 8; r++) acc[r] = bb;

#pragma unroll 4
    for (int k = 0; k < 128; k++) {
        float w = sW[k * 128 + t];
#pragma unroll
        for (int r = 0; r < 8; r++) acc[r] += sX[r * 128 + k] * w;
    }
#pragma unroll
    for (int r = 0; r < 8; r++) Y[(size_t)(row0 + r) * 128 + t] = acc[r];
}

// ---------------- edge attention: ex = exp(score), denom += ex --------------
// One thread per (edge, head). Softmax shift dropped (shift-invariant;
// scores are O(0.2) here so exp cannot overflow).
__global__ void edge_attn_kernel(const float* __restrict__ xl,
                                 const float* __restrict__ xr,
                                 const float* __restrict__ att,  // [8,16]
                                 const int* __restrict__ ei,     // [2,E] int32
                                 float* __restrict__ ex,         // [ETOT,8]
                                 float* __restrict__ den) {      // [N,8]
    int tid = blockIdx.x * 256 + threadIdx.x;
    if (tid >= ETOT * HEADS) return;
    int e = tid >> 3;
    int h = tid & 7;
    int s, d;
    if (e < NEDGE) { s = ei[e]; d = ei[NEDGE + e]; }
    else { s = d = e - NEDGE; }

    const float4* pl = (const float4*)(xl + (size_t)s * FDIM + h * CH);
    const float4* pr = (const float4*)(xr + (size_t)d * FDIM + h * CH);
    const float4* pa = (const float4*)(att + h * CH);
    float sc = 0.f;
#pragma unroll
    for (int i = 0; i < 4; i++) {
        float4 a = pl[i], bvec = pr[i], w = pa[i];
        float v;
        v = a.x + bvec.x; v = v > 0.f ? v : 0.2f * v; sc += v * w.x;
        v = a.y + bvec.y; v = v > 0.f ? v : 0.2f * v; sc += v * w.y;
        v = a.z + bvec.z; v = v > 0.f ? v : 0.2f * v; sc += v * w.z;
        v = a.w + bvec.w; v = v > 0.f ? v : 0.2f * v; sc += v * w.w;
    }
    float ev = expf(sc);
    ex[tid] = ev;
    atomicAdd(&den[(size_t)d * HEADS + h], ev);
}

// ---------------- scatter: out[dst] += alpha * xl[src] ----------------------
// 32 threads per edge; each thread handles one float4 (4 channels).
__global__ void edge_scatter_kernel(const float* __restrict__ xl,
                                    const float* __restrict__ ex,
                                    const float* __restrict__ den,
                                    const int* __restrict__ ei,
                                    float* __restrict__ out) {
    int gid = blockIdx.x * 256 + threadIdx.x;
    int e = gid >> 5;
    if (e >= ETOT) return;
    int lane = gid & 31;
    int s, d;
    if (e < NEDGE) { s = ei[e]; d = ei[NEDGE + e]; }
    else { s = d = e - NEDGE; }
    int h = lane >> 2;
    float alpha = ex[(size_t)e * HEADS + h] / den[(size_t)d * HEADS + h];
    float4 v = ((const float4*)(xl + (size_t)s * FDIM))[lane];
    float* o = out + (size_t)d * FDIM + lane * 4;
    atomicAdd(o + 0, v.x * alpha);
    atomicAdd(o + 1, v.y * alpha);
    atomicAdd(o + 2, v.z * alpha);
    atomicAdd(o + 3, v.w * alpha);
}

// ---------------- bias + BatchNorm(eval) + ELU ------------------------------
__global__ void bn_elu_kernel(const float* __restrict__ acc,
                              const float* __restrict__ bias,
                              const float* __restrict__ bw, const float* __restrict__ bb,
                              const float* __restrict__ rm, const float* __restrict__ rv,
                              float* __restrict__ h1) {
    int i = blockIdx.x * 256 + threadIdx.x;
    if (i >= NNODE * FDIM) return;
    int c = i & 127;
    float v = acc[i] + bias[c];
    v = (v - rm[c]) * rsqrtf(rv[c] + 1e-5f) * bw[c] + bb[c];
    h1[i] = v > 0.f ? v : expm1f(v);
}

// ---------------- final: mean-over-heads + bias2 + skip GEMM + LayerNorm ----
__global__ void final_kernel(const float* __restrict__ out2,
                             const float* __restrict__ bias2,  // [16]
                             const float* __restrict__ x,      // [N,128]
                             const float* __restrict__ Wskip,  // [16,128]
                             const float* __restrict__ lnw, const float* __restrict__ lnb,
                             float* __restrict__ yout) {
    __shared__ float sWs[128 * 16];   // transposed: sWs[k*16+j]
    __shared__ float sX[16 * 132];    // padded rows
    int t = threadIdx.x;              // 0..255
    for (int i = t; i < 16 * 128; i += 256) {
        int j = i >> 7, k = i & 127;
        sWs[k * 16 + j] = Wskip[i];
    }
    int n0 = blockIdx.x * 16;
    for (int i = t; i < 16 * 128; i += 256) {
        int r = i >> 7, k = i & 127;
        sX[r * 132 + k] = x[(size_t)(n0 + r) * 128 + k];
    }
    __syncthreads();

    int warp = t >> 5, lane = t & 31;
    int nl = warp * 2 + (lane >> 4);  // local node 0..15
    int n = n0 + nl;
    int j = lane & 15;

    // mean over heads
    const float* o2 = out2 + (size_t)n * FDIM;
    float m = 0.f;
#pragma unroll
    for (int h = 0; h < HEADS; h++) m += o2[h * CH + j];
    m *= 0.125f;

    // skip connection: dot(x[n], Wskip[j])
    const float* xs = sX + nl * 132;
    float skip = 0.f;
#pragma unroll 8
    for (int k = 0; k < 128; k++) skip += xs[k] * sWs[k * 16 + j];

    float y = m + bias2[j] + skip;

    // LayerNorm over 16 lanes (xor shuffles stay within 16-lane groups)
    float sum = y;
#pragma unroll
    for (int dd = 1; dd < 16; dd <<= 1) sum += __shfl_xor_sync(0xffffffffu, sum, dd);
    float mu = sum * (1.f / 16.f);
    float diff = y - mu;
    float vs = diff * diff;
#pragma unroll
    for (int dd = 1; dd < 16; dd <<= 1) vs += __shfl_xor_sync(0xffffffffu, vs, dd);
    float var = vs * (1.f / 16.f);
    yout[(size_t)n * 16 + j] = diff * rsqrtf(var + 1e-5f) * lnw[j] + lnb[j];
}

// ---------------- launch ----------------------------------------------------
extern "C" void kernel_launch(void* const* d_in, const int* in_sizes, int n_in,
                              void* d_out, int out_size) {
    const float* x      = (const float*)d_in[0];
    const int*   ei     = (const int*)d_in[1];   // int32 (JAX x64 disabled)
    const float* Wl1    = (const float*)d_in[2];
    const float* bl1    = (const float*)d_in[3];
    const float* Wr1    = (const float*)d_in[4];
    const float* br1    = (const float*)d_in[5];
    const float* att1   = (const float*)d_in[6];
    const float* bias1  = (const float*)d_in[7];
    const float* bn_w   = (const float*)d_in[8];
    const float* bn_b   = (const float*)d_in[9];
    const float* bn_rm  = (const float*)d_in[10];
    const float* bn_rv  = (const float*)d_in[11];
    const float* Wl2    = (const float*)d_in[12];
    const float* bl2    = (const float*)d_in[13];
    const float* Wr2    = (const float*)d_in[14];
    const float* br2    = (const float*)d_in[15];
    const float* att2   = (const float*)d_in[16];
    const float* bias2  = (const float*)d_in[17];
    const float* Wskip  = (const float*)d_in[18];
    const float* ln_w   = (const float*)d_in[19];
    const float* ln_b   = (const float*)d_in[20];
    float* yout = (float*)d_out;

    float* scratch = nullptr;
    cudaGetSymbolAddress((void**)&scratch, g_scratch);
    float* xl1  = scratch + OFF_XL1;
    float* xr1  = scratch + OFF_XR1;
    float* ex1  = scratch + OFF_EX1;
    float* den1 = scratch + OFF_DEN1;
    float* acc1 = scratch + OFF_ACC1;
    float* h1   = scratch + OFF_H1;
    float* xl2  = scratch + OFF_XL2;
    float* xr2  = scratch + OFF_XR2;
    float* ex2  = scratch + OFF_EX2;
    float* den2 = scratch + OFF_DEN2;
    float* out2 = scratch + OFF_OUT2;

    const int gemm_smem = (128 * 128 + 8 * 128) * sizeof(float);  // 68KB
    cudaFuncSetAttribute(gemm128_kernel, cudaFuncAttributeMaxDynamicSharedMemorySize, gemm_smem);

    zero_scratch_kernel<<<2048, 256>>>();

    // ---- layer 1 ----
    gemm128_kernel<<<NNODE / 8, 128, gemm_smem>>>(x, Wl1, bl1, xl1, NNODE);
    gemm128_kernel<<<NNODE / 8, 128, gemm_smem>>>(x, Wr1, br1, xr1, NNODE);

    int attn_threads = ETOT * HEADS;
    edge_attn_kernel<<<(attn_threads + 255) / 256, 256>>>(xl1, xr1, att1, ei, ex1, den1);

    int scat_threads = ETOT * 32;
    edge_scatter_kernel<<<(scat_threads + 255) / 256, 256>>>(xl1, ex1, den1, ei, acc1);

    bn_elu_kernel<<<(NNODE * FDIM + 255) / 256, 256>>>(acc1, bias1, bn_w, bn_b, bn_rm, bn_rv, h1);

    // ---- layer 2 ----
    gemm128_kernel<<<NNODE / 8, 128, gemm_smem>>>(h1, Wl2, bl2, xl2, NNODE);
    gemm128_kernel<<<NNODE / 8, 128, gemm_smem>>>(h1, Wr2, br2, xr2, NNODE);

    edge_attn_kernel<<<(attn_threads + 255) / 256, 256>>>(xl2, xr2, att2, ei, ex2, den2);
    edge_scatter_kernel<<<(scat_threads + 255) / 256, 256>>>(xl2, ex2, den2, ei, out2);

    // ---- epilogue: mean heads + bias2 + skip + LayerNorm ----
    final_kernel<<<NNODE / 16, 256>>>(out2, bias2, x, Wskip, ln_w, ln_b, yout);
}

// round 8
// speedup vs baseline: 3.0586x; 3.0586x over previous
#include <cuda_runtime.h>
#include <cuda_bf16.h>
#include <math.h>

#define NNODE 50000
#define NEDGE 800000
#define ETOT  (NEDGE + NNODE)   // 850000 with self loops
#define FDIM  128
#define HEADS 8
#define CH    16
#define NF    ((size_t)NNODE * FDIM)   // 6.4M floats

// ---------------- scratch ----------------------------------------------------
// 4 node-feature buffers (reused across layers to stay L2-resident)
__device__ float g_fbuf[4 * NNODE * FDIM];
__device__ int   g_counts[NNODE];
__device__ int   g_rowptr[NNODE + 1];
__device__ int   g_wptr[NNODE];
__device__ int   g_esrc[ETOT];

#define BUF_XL  (g_fbuf_ptr + 0 * NF)
#define BUF_XR  (g_fbuf_ptr + 1 * NF)
#define BUF_ACC (g_fbuf_ptr + 2 * NF)
#define BUF_H   (g_fbuf_ptr + 3 * NF)

// ---------------- CSR build --------------------------------------------------
__global__ void zero_counts_kernel() {
    int i = blockIdx.x * 256 + threadIdx.x;
    if (i < NNODE) g_counts[i] = 0;
}

__global__ void hist_kernel(const int* __restrict__ ei) {
    int e = blockIdx.x * 256 + threadIdx.x;
    if (e >= ETOT) return;
    int d = (e < NEDGE) ? ei[NEDGE + e] : (e - NEDGE);
    atomicAdd(&g_counts[d], 1);
}

// single-block exclusive scan of g_counts -> g_rowptr / g_wptr
__global__ void scan_kernel() {
    __shared__ int ssum[1024];
    const int CHUNK = 49;                 // 1024*49 = 50176 >= 50000
    int t = threadIdx.x;
    int beg = t * CHUNK;
    int end = beg + CHUNK; if (end > NNODE) end = NNODE;
    int s = 0;
    for (int i = beg; i < end; i++) s += g_counts[i];
    ssum[t] = s;
    __syncthreads();
    for (int off = 1; off < 1024; off <<= 1) {
        int v = (t >= off) ? ssum[t - off] : 0;
        __syncthreads();
        ssum[t] += v;
        __syncthreads();
    }
    int run = (t == 0) ? 0 : ssum[t - 1];
    for (int i = beg; i < end; i++) {
        g_rowptr[i] = run;
        g_wptr[i]   = run;
        run += g_counts[i];
    }
    if (t == 1023) g_rowptr[NNODE] = ETOT;
}

__global__ void fill_kernel(const int* __restrict__ ei) {
    int e = blockIdx.x * 256 + threadIdx.x;
    if (e >= ETOT) return;
    int s, d;
    if (e < NEDGE) { s = ei[e]; d = ei[NEDGE + e]; }
    else { s = d = e - NEDGE; }
    int pos = atomicAdd(&g_wptr[d], 1);
    g_esrc[pos] = s;
}

// ---------------- GEMM: Y[M,128] = X[M,128] @ W[128,128]^T + b ---------------
// 256 threads, block tile 128x128, thread tile 8x8. FFMA-issue bound.
__global__ void gemm128_kernel(const float* __restrict__ X,
                               const float* __restrict__ W,
                               const float* __restrict__ b,
                               float* __restrict__ Y, int M) {
    extern __shared__ float sm[];
    float* sB = sm;            // [k*128+n]  (W transposed)
    float* sA = sm + 16384;    // [m*128+k]  (X rows, straight copy)
    int tid = threadIdx.x;
    int row0 = blockIdx.x * 128;

    if (tid < 128) {
        // transpose W row 'tid' into sB columns — conflict-free STS
        const float4* wr = (const float4*)(W + (size_t)tid * 128);
#pragma unroll
        for (int i = 0; i < 32; i++) {
            float4 v = wr[i];
            int k = i * 4;
            sB[(k + 0) * 128 + tid] = v.x;
            sB[(k + 1) * 128 + tid] = v.y;
            sB[(k + 2) * 128 + tid] = v.z;
            sB[(k + 3) * 128 + tid] = v.w;
        }
    } else {
        int t = tid - 128;
        float4* sA4 = (float4*)sA;
        const float4* X4 = (const float4*)X;
#pragma unroll
        for (int i = 0; i < 32; i++) {
            int idx = t + i * 128;          // 0..4095
            int r = idx >> 5;
            float4 v = make_float4(0.f, 0.f, 0.f, 0.f);
            if (row0 + r < M) v = X4[(size_t)(row0 + r) * 32 + (idx & 31)];
            sA4[idx] = v;
        }
    }
    __syncthreads();

    int nt = tid & 15, mt = tid >> 4;
    int n0 = nt * 8, m0 = mt * 8;

    float acc[8][8];
    float bj[8];
#pragma unroll
    for (int j = 0; j < 8; j++) bj[j] = b[n0 + j];
#pragma unroll
    for (int im = 0; im < 8; im++)
#pragma unroll
        for (int jn = 0; jn < 8; jn++) acc[im][jn] = bj[jn];

#pragma unroll 2
    for (int k = 0; k < 128; k++) {
        float areg[8];
#pragma unroll
        for (int im = 0; im < 8; im++) areg[im] = sA[(m0 + im) * 128 + k];
        float4 b0 = *(const float4*)&sB[k * 128 + n0];
        float4 b1 = *(const float4*)&sB[k * 128 + n0 + 4];
        float breg[8] = {b0.x, b0.y, b0.z, b0.w, b1.x, b1.y, b1.z, b1.w};
#pragma unroll
        for (int im = 0; im < 8; im++)
#pragma unroll
            for (int jn = 0; jn < 8; jn++) acc[im][jn] += areg[im] * breg[jn];
    }

#pragma unroll
    for (int im = 0; im < 8; im++) {
        int row = row0 + m0 + im;
        if (row < M) {
            float4* yo = (float4*)(Y + (size_t)row * 128 + n0);
            yo[0] = make_float4(acc[im][0], acc[im][1], acc[im][2], acc[im][3]);
            yo[1] = make_float4(acc[im][4], acc[im][5], acc[im][6], acc[im][7]);
        }
    }
}

// ---------------- fused GAT aggregation --------------------------------------
// One warp per destination node. Single pass: score -> exp -> denom -> weighted
// sum, all in registers. Softmax shift dropped (shift-invariant, scores O(0.2)).
__global__ void gat_agg_kernel(const float* __restrict__ xl,
                               const float* __restrict__ xr,
                               const float* __restrict__ att,   // [8,16]
                               float* __restrict__ out) {
    int w = (blockIdx.x * blockDim.x + threadIdx.x) >> 5;
    if (w >= NNODE) return;
    int l = threadIdx.x & 31;

    const float4* xl4 = (const float4*)xl;
    float4 r = ((const float4*)xr)[(size_t)w * 32 + l];
    float4 a = ((const float4*)att)[l];

    int beg = g_rowptr[w], end = g_rowptr[w + 1];
    float4 acc = make_float4(0.f, 0.f, 0.f, 0.f);
    float den = 0.f;

    for (int base = beg; base < end; base += 32) {
        int n = end - base; if (n > 32) n = 32;
        int sid = (base + l < end) ? g_esrc[base + l] : 0;
        for (int j = 0; j < n; j++) {
            int s = __shfl_sync(0xffffffffu, sid, j);
            float4 xs = xl4[(size_t)s * 32 + l];
            float tx = xs.x + r.x; tx = tx > 0.f ? tx : 0.2f * tx;
            float ty = xs.y + r.y; ty = ty > 0.f ? ty : 0.2f * ty;
            float tz = xs.z + r.z; tz = tz > 0.f ? tz : 0.2f * tz;
            float tw = xs.w + r.w; tw = tw > 0.f ? tw : 0.2f * tw;
            float p = tx * a.x + ty * a.y + tz * a.z + tw * a.w;
            p += __shfl_xor_sync(0xffffffffu, p, 1);
            p += __shfl_xor_sync(0xffffffffu, p, 2);   // head score in all 4 lanes
            float ev = __expf(p);
            den += ev;
            acc.x += ev * xs.x; acc.y += ev * xs.y;
            acc.z += ev * xs.z; acc.w += ev * xs.w;
        }
    }
    float inv = 1.f / den;   // den identical within each 4-lane head group
    ((float4*)out)[(size_t)w * 32 + l] =
        make_float4(acc.x * inv, acc.y * inv, acc.z * inv, acc.w * inv);
}

// ---------------- bias + BatchNorm(eval) + ELU -------------------------------
__global__ void bn_elu_kernel(const float* __restrict__ acc,
                              const float* __restrict__ bias,
                              const float* __restrict__ bw, const float* __restrict__ bb,
                              const float* __restrict__ rm, const float* __restrict__ rv,
                              float* __restrict__ h1) {
    int i = blockIdx.x * 256 + threadIdx.x;
    if (i >= NNODE * FDIM) return;
    int c = i & 127;
    float v = acc[i] + bias[c];
    v = (v - rm[c]) * rsqrtf(rv[c] + 1e-5f) * bw[c] + bb[c];
    h1[i] = v > 0.f ? v : expm1f(v);
}

// ---------------- final: mean heads + bias2 + skip GEMM + LayerNorm ----------
__global__ void final_kernel(const float* __restrict__ out2,
                             const float* __restrict__ bias2,
                             const float* __restrict__ x,
                             const float* __restrict__ Wskip,  // [16,128]
                             const float* __restrict__ lnw, const float* __restrict__ lnb,
                             float* __restrict__ yout) {
    __shared__ float sWs[128 * 16];
    __shared__ float sX[16 * 132];
    int t = threadIdx.x;
    for (int i = t; i < 16 * 128; i += 256) {
        int j = i >> 7, k = i & 127;
        sWs[k * 16 + j] = Wskip[i];
    }
    int n0 = blockIdx.x * 16;
    for (int i = t; i < 16 * 128; i += 256) {
        int r = i >> 7, k = i & 127;
        sX[r * 132 + k] = x[(size_t)(n0 + r) * 128 + k];
    }
    __syncthreads();

    int warp = t >> 5, lane = t & 31;
    int nl = warp * 2 + (lane >> 4);
    int n = n0 + nl;
    int j = lane & 15;

    const float* o2 = out2 + (size_t)n * FDIM;
    float m = 0.f;
#pragma unroll
    for (int h = 0; h < HEADS; h++) m += o2[h * CH + j];
    m *= 0.125f;

    const float* xs = sX + nl * 132;
    float skip = 0.f;
#pragma unroll 8
    for (int k = 0; k < 128; k++) skip += xs[k] * sWs[k * 16 + j];

    float y = m + bias2[j] + skip;

    float sum = y;
#pragma unroll
    for (int dd = 1; dd < 16; dd <<= 1) sum += __shfl_xor_sync(0xffffffffu, sum, dd);
    float mu = sum * (1.f / 16.f);
    float diff = y - mu;
    float vs = diff * diff;
#pragma unroll
    for (int dd = 1; dd < 16; dd <<= 1) vs += __shfl_xor_sync(0xffffffffu, vs, dd);
    float var = vs * (1.f / 16.f);
    yout[(size_t)n * 16 + j] = diff * rsqrtf(var + 1e-5f) * lnw[j] + lnb[j];
}

// ---------------- launch -----------------------------------------------------
extern "C" void kernel_launch(void* const* d_in, const int* in_sizes, int n_in,
                              void* d_out, int out_size) {
    const float* x      = (const float*)d_in[0];
    const int*   ei     = (const int*)d_in[1];
    const float* Wl1    = (const float*)d_in[2];
    const float* bl1    = (const float*)d_in[3];
    const float* Wr1    = (const float*)d_in[4];
    const float* br1    = (const float*)d_in[5];
    const float* att1   = (const float*)d_in[6];
    const float* bias1  = (const float*)d_in[7];
    const float* bn_w   = (const float*)d_in[8];
    const float* bn_b   = (const float*)d_in[9];
    const float* bn_rm  = (const float*)d_in[10];
    const float* bn_rv  = (const float*)d_in[11];
    const float* Wl2    = (const float*)d_in[12];
    const float* bl2    = (const float*)d_in[13];
    const float* Wr2    = (const float*)d_in[14];
    const float* br2    = (const float*)d_in[15];
    const float* att2   = (const float*)d_in[16];
    const float* bias2  = (const float*)d_in[17];
    const float* Wskip  = (const float*)d_in[18];
    const float* ln_w   = (const float*)d_in[19];
    const float* ln_b   = (const float*)d_in[20];
    float* yout = (float*)d_out;

    float* g_fbuf_ptr = nullptr;
    cudaGetSymbolAddress((void**)&g_fbuf_ptr, g_fbuf);
    float* XL  = BUF_XL;
    float* XR  = BUF_XR;
    float* ACC = BUF_ACC;
    float* H   = BUF_H;

    const int gemm_smem = 2 * 128 * 128 * sizeof(float);  // 128KB
    cudaFuncSetAttribute(gemm128_kernel, cudaFuncAttributeMaxDynamicSharedMemorySize, gemm_smem);
    const int gemm_grid = (NNODE + 127) / 128;            // 391

    // ---- CSR build (shared by both layers) ----
    zero_counts_kernel<<<(NNODE + 255) / 256, 256>>>();
    hist_kernel<<<(ETOT + 255) / 256, 256>>>(ei);
    scan_kernel<<<1, 1024>>>();
    fill_kernel<<<(ETOT + 255) / 256, 256>>>(ei);

    // ---- layer 1 ----
    gemm128_kernel<<<gemm_grid, 256, gemm_smem>>>(x, Wl1, bl1, XL, NNODE);
    gemm128_kernel<<<gemm_grid, 256, gemm_smem>>>(x, Wr1, br1, XR, NNODE);
    gat_agg_kernel<<<(NNODE * 32 + 255) / 256, 256>>>(XL, XR, att1, ACC);
    bn_elu_kernel<<<(NNODE * FDIM + 255) / 256, 256>>>(ACC, bias1, bn_w, bn_b, bn_rm, bn_rv, H);

    // ---- layer 2 ----
    gemm128_kernel<<<gemm_grid, 256, gemm_smem>>>(H, Wl2, bl2, XL, NNODE);
    gemm128_kernel<<<gemm_grid, 256, gemm_smem>>>(H, Wr2, br2, XR, NNODE);
    gat_agg_kernel<<<(NNODE * 32 + 255) / 256, 256>>>(XL, XR, att2, ACC);

    // ---- epilogue ----
    final_kernel<<<NNODE / 16, 256>>>(ACC, bias2, x, Wskip, ln_w, ln_b, yout);
}

// round 11
// speedup vs baseline: 3.8554x; 1.2605x over previous
#include <cuda_runtime.h>
#include <cuda_bf16.h>
#include <math.h>
#include <stdint.h>

#define NNODE 50000
#define NEDGE 800000
#define ETOT  (NEDGE + NNODE)
#define FDIM  128
#define HEADS 8
#define CH    16
#define NF    ((size_t)NNODE * FDIM)

// ---------------- static scratch --------------------------------------------
__device__ float g_XL[NNODE * FDIM];
__device__ float g_XR[NNODE * FDIM];
__device__ float g_ACC[NNODE * FDIM];
__device__ float g_H[NNODE * FDIM];
__device__ __nv_bfloat16 g_whi[4 * 16384];   // Wl1,Wr1,Wl2,Wr2 (row-major each)
__device__ __nv_bfloat16 g_wlo[4 * 16384];
__device__ int g_counts[NNODE];
__device__ int g_rowptr[NNODE + 1];
__device__ int g_wptr[NNODE];
__device__ int g_esrc[ETOT];

__device__ __forceinline__ uint32_t smem_u32(const void* p) {
    uint32_t a;
    asm("{ .reg .u64 t; cvta.to.shared.u64 t, %1; cvt.u32.u64 %0, t; }" : "=r"(a) : "l"(p));
    return a;
}

// ---------------- CSR build --------------------------------------------------
__global__ void zero_counts_kernel() {
    int i = blockIdx.x * 256 + threadIdx.x;
    if (i < NNODE) g_counts[i] = 0;
}
__global__ void hist_kernel(const int* __restrict__ ei) {
    int e = blockIdx.x * 256 + threadIdx.x;
    if (e >= ETOT) return;
    int d = (e < NEDGE) ? ei[NEDGE + e] : (e - NEDGE);
    atomicAdd(&g_counts[d], 1);
}
__global__ void scan_kernel() {
    __shared__ int ssum[1024];
    const int CHUNK = 49;
    int t = threadIdx.x;
    int beg = t * CHUNK;
    int end = beg + CHUNK; if (end > NNODE) end = NNODE;
    int s = 0;
    for (int i = beg; i < end; i++) s += g_counts[i];
    ssum[t] = s;
    __syncthreads();
    for (int off = 1; off < 1024; off <<= 1) {
        int v = (t >= off) ? ssum[t - off] : 0;
        __syncthreads();
        ssum[t] += v;
        __syncthreads();
    }
    int run = (t == 0) ? 0 : ssum[t - 1];
    for (int i = beg; i < end; i++) {
        g_rowptr[i] = run;
        g_wptr[i]   = run;
        run += g_counts[i];
    }
    if (t == 1023) g_rowptr[NNODE] = ETOT;
}
__global__ void fill_kernel(const int* __restrict__ ei) {
    int e = blockIdx.x * 256 + threadIdx.x;
    if (e >= ETOT) return;
    int s, d;
    if (e < NEDGE) { s = ei[e]; d = ei[NEDGE + e]; }
    else { s = d = e - NEDGE; }
    int pos = atomicAdd(&g_wptr[d], 1);
    g_esrc[pos] = s;
}

// ---------------- weight hi/lo conversion ------------------------------------
__global__ void conv_w_kernel(const float* __restrict__ Wl1, const float* __restrict__ Wr1,
                              const float* __restrict__ Wl2, const float* __restrict__ Wr2) {
    int i = blockIdx.x * 256 + threadIdx.x;
    if (i >= 4 * 16384) return;
    int m = i >> 14, k = i & 16383;
    const float* src = (m == 0) ? Wl1 : (m == 1) ? Wr1 : (m == 2) ? Wl2 : Wr2;
    float v = src[k];
    __nv_bfloat16 h = __float2bfloat16_rn(v);
    g_whi[i] = h;
    g_wlo[i] = __float2bfloat16_rn(v - __bfloat162float(h));
}

// ---------------- dual GEMM via mma.sync bf16 hi/lo 3-pass -------------------
// Y{l,r}[M,128] = A[M,128] @ W{l,r}^T + b.  B = [Wl;Wr] as 256 rows x 128 k.
// CTA: 128 rows x 256 cols, K=128 resident.  512 thr = 16 warps, warp 32x64.
#define PAD_ROW 272                  // 136 bf16 per row (128 + 8 pad), bytes
#define SM_A_HI 0
#define SM_A_LO (128 * PAD_ROW)      // 34816
#define SM_B_HI (2 * 128 * PAD_ROW)  // 69632
#define SM_B_LO (SM_B_HI + 256 * PAD_ROW)
#define SM_TOT  (SM_B_LO + 256 * PAD_ROW)   // 208896

#define LDM4(r, addr) \
    asm volatile("ldmatrix.sync.aligned.m8n8.x4.shared.b16 {%0,%1,%2,%3}, [%4];" \
        : "=r"((r)[0]), "=r"((r)[1]), "=r"((r)[2]), "=r"((r)[3]) : "r"(addr))

#define MMA16816(c, a, b0, b1) \
    asm volatile("mma.sync.aligned.m16n8k16.row.col.f32.bf16.bf16.f32 " \
        "{%0,%1,%2,%3}, {%4,%5,%6,%7}, {%8,%9}, {%0,%1,%2,%3};" \
        : "+f"((c)[0]), "+f"((c)[1]), "+f"((c)[2]), "+f"((c)[3]) \
        : "r"((a)[0]), "r"((a)[1]), "r"((a)[2]), "r"((a)[3]), "r"(b0), "r"(b1))

__device__ __forceinline__ uint32_t pack2(float x, float y) {
    __nv_bfloat162 t;
    t.x = __float2bfloat16_rn(x);
    t.y = __float2bfloat16_rn(y);
    return *(uint32_t*)&t;
}

__global__ void __launch_bounds__(512, 1)
gemm_mma_kernel(const float* __restrict__ A,
                const __nv_bfloat16* __restrict__ Bhi,
                const __nv_bfloat16* __restrict__ Blo,
                const float* __restrict__ bl, const float* __restrict__ br,
                float* __restrict__ Yl, float* __restrict__ Yr, int M) {
    extern __shared__ char sm[];
    uint32_t sbase = smem_u32(sm);
    int tid = threadIdx.x;
    int row0 = blockIdx.x * 128;

    // ---- load A fp32 -> split hi/lo into SMEM (8 floats / unit) ----
#pragma unroll
    for (int i = 0; i < 4; i++) {
        int idx = tid + i * 512;          // 0..2047
        int r = idx >> 4;                 // 0..127
        int kc = idx & 15;                // 16B chunk (8 bf16)
        int grow = row0 + r;
        float4 v0 = make_float4(0.f, 0.f, 0.f, 0.f), v1 = v0;
        if (grow < M) {
            const float4* src = (const float4*)(A + (size_t)grow * 128 + kc * 8);
            v0 = src[0]; v1 = src[1];
        }
        uint4 hi, lo;
        hi.x = pack2(v0.x, v0.y); hi.y = pack2(v0.z, v0.w);
        hi.z = pack2(v1.x, v1.y); hi.w = pack2(v1.z, v1.w);
        float h;
        h = __bfloat162float(__float2bfloat16_rn(v0.x));
        float lx = v0.x - h;
        h = __bfloat162float(__float2bfloat16_rn(v0.y));
        float ly = v0.y - h;
        h = __bfloat162float(__float2bfloat16_rn(v0.z));
        float lz = v0.z - h;
        h = __bfloat162float(__float2bfloat16_rn(v0.w));
        float lw = v0.w - h;
        lo.x = pack2(lx, ly); lo.y = pack2(lz, lw);
        h = __bfloat162float(__float2bfloat16_rn(v1.x));
        lx = v1.x - h;
        h = __bfloat162float(__float2bfloat16_rn(v1.y));
        ly = v1.y - h;
        h = __bfloat162float(__float2bfloat16_rn(v1.z));
        lz = v1.z - h;
        h = __bfloat162float(__float2bfloat16_rn(v1.w));
        lw = v1.w - h;
        lo.z = pack2(lx, ly); lo.w = pack2(lz, lw);
        uint32_t off = (uint32_t)r * PAD_ROW + (uint32_t)kc * 16;
        *(uint4*)(sm + SM_A_HI + off) = hi;
        *(uint4*)(sm + SM_A_LO + off) = lo;
    }
    // ---- copy B hi/lo (preconverted bf16) ----
#pragma unroll
    for (int i = 0; i < 8; i++) {
        int idx = tid + i * 512;          // 0..4095
        int r = idx >> 4;                 // 0..255
        int kc = idx & 15;
        uint32_t off = (uint32_t)r * PAD_ROW + (uint32_t)kc * 16;
        *(uint4*)(sm + SM_B_HI + off) = *(const uint4*)(Bhi + (size_t)r * 128 + kc * 8);
        *(uint4*)(sm + SM_B_LO + off) = *(const uint4*)(Blo + (size_t)r * 128 + kc * 8);
    }
    __syncthreads();

    int lane = tid & 31, wid = tid >> 5;
    int warp_m = wid & 3, warp_n = wid >> 2;

    // ldmatrix lane addresses
    uint32_t aoff0 = (uint32_t)(warp_m * 32 + (lane & 15)) * PAD_ROW + ((lane >> 4) * 16);
    uint32_t aoff1 = aoff0 + 16 * PAD_ROW;
    uint32_t aHi0 = sbase + SM_A_HI + aoff0, aHi1 = sbase + SM_A_HI + aoff1;
    uint32_t aLo0 = sbase + SM_A_LO + aoff0, aLo1 = sbase + SM_A_LO + aoff1;
    uint32_t boff = (uint32_t)(warp_n * 64 + (lane & 7) + ((lane >> 4) & 1) * 8) * PAD_ROW
                  + (((lane >> 3) & 1) * 16);
    uint32_t bHiB = sbase + SM_B_HI + boff;
    uint32_t bLoB = sbase + SM_B_LO + boff;

    float c[2][8][4];
#pragma unroll
    for (int t = 0; t < 2; t++)
#pragma unroll
        for (int n = 0; n < 8; n++)
#pragma unroll
            for (int q = 0; q < 4; q++) c[t][n][q] = 0.f;

#pragma unroll
    for (int p = 0; p < 3; p++) {
        uint32_t ab0 = (p < 2) ? aHi0 : aLo0;
        uint32_t ab1 = (p < 2) ? aHi1 : aLo1;
        uint32_t bb  = (p == 1) ? bLoB : bHiB;
#pragma unroll
        for (int ks = 0; ks < 8; ks++) {
            uint32_t kb = ks * 32;
            uint32_t a0[4], a1[4];
            LDM4(a0, ab0 + kb);
            LDM4(a1, ab1 + kb);
#pragma unroll
            for (int g = 0; g < 4; g++) {
                uint32_t b[4];
                LDM4(b, bb + g * (16 * PAD_ROW) + kb);
                MMA16816(c[0][2 * g],     a0, b[0], b[1]);
                MMA16816(c[0][2 * g + 1], a0, b[2], b[3]);
                MMA16816(c[1][2 * g],     a1, b[0], b[1]);
                MMA16816(c[1][2 * g + 1], a1, b[2], b[3]);
            }
        }
    }

    // ---- epilogue: bias + store ----
    const float* bias = (warp_n < 2) ? bl : br;
    float* Y = (warp_n < 2) ? Yl : Yr;
    int ncol0 = (warp_n & 1) * 64;
#pragma unroll
    for (int t = 0; t < 2; t++) {
        int r = row0 + warp_m * 32 + t * 16 + (lane >> 2);
#pragma unroll
        for (int nt = 0; nt < 8; nt++) {
            int col = ncol0 + nt * 8 + (lane & 3) * 2;
            float b0 = bias[col], b1 = bias[col + 1];
            if (r < M)
                *(float2*)(Y + (size_t)r * 128 + col) =
                    make_float2(c[t][nt][0] + b0, c[t][nt][1] + b1);
            if (r + 8 < M)
                *(float2*)(Y + (size_t)(r + 8) * 128 + col) =
                    make_float2(c[t][nt][2] + b0, c[t][nt][3] + b1);
        }
    }
}

// ---------------- fused GAT aggregation (one warp / dst node) ----------------
__global__ void gat_agg_kernel(const float* __restrict__ xl,
                               const float* __restrict__ xr,
                               const float* __restrict__ att,
                               float* __restrict__ out) {
    int w = (blockIdx.x * blockDim.x + threadIdx.x) >> 5;
    if (w >= NNODE) return;
    int l = threadIdx.x & 31;

    const float4* xl4 = (const float4*)xl;
    float4 r = ((const float4*)xr)[(size_t)w * 32 + l];
    float4 a = ((const float4*)att)[l];

    int beg = g_rowptr[w], end = g_rowptr[w + 1];
    float4 acc = make_float4(0.f, 0.f, 0.f, 0.f);
    float den = 0.f;

    for (int base = beg; base < end; base += 32) {
        int n = end - base; if (n > 32) n = 32;
        int sid = (base + l < end) ? g_esrc[base + l] : 0;
        for (int j = 0; j < n; j++) {
            int s = __shfl_sync(0xffffffffu, sid, j);
            float4 xs = xl4[(size_t)s * 32 + l];
            float tx = xs.x + r.x; tx = tx > 0.f ? tx : 0.2f * tx;
            float ty = xs.y + r.y; ty = ty > 0.f ? ty : 0.2f * ty;
            float tz = xs.z + r.z; tz = tz > 0.f ? tz : 0.2f * tz;
            float tw = xs.w + r.w; tw = tw > 0.f ? tw : 0.2f * tw;
            float p = tx * a.x + ty * a.y + tz * a.z + tw * a.w;
            p += __shfl_xor_sync(0xffffffffu, p, 1);
            p += __shfl_xor_sync(0xffffffffu, p, 2);
            float ev = __expf(p);
            den += ev;
            acc.x += ev * xs.x; acc.y += ev * xs.y;
            acc.z += ev * xs.z; acc.w += ev * xs.w;
        }
    }
    float inv = 1.f / den;
    ((float4*)out)[(size_t)w * 32 + l] =
        make_float4(acc.x * inv, acc.y * inv, acc.z * inv, acc.w * inv);
}

// ---------------- bias + BN(eval) + ELU --------------------------------------
__global__ void bn_elu_kernel(const float* __restrict__ acc,
                              const float* __restrict__ bias,
                              const float* __restrict__ bw, const float* __restrict__ bb,
                              const float* __restrict__ rm, const float* __restrict__ rv,
                              float* __restrict__ h1) {
    int i = blockIdx.x * 256 + threadIdx.x;
    if (i >= NNODE * FDIM) return;
    int c = i & 127;
    float v = acc[i] + bias[c];
    v = (v - rm[c]) * rsqrtf(rv[c] + 1e-5f) * bw[c] + bb[c];
    h1[i] = v > 0.f ? v : expm1f(v);
}

// ---------------- final: mean heads + bias2 + skip GEMM + LayerNorm ----------
__global__ void final_kernel(const float* __restrict__ out2,
                             const float* __restrict__ bias2,
                             const float* __restrict__ x,
                             const float* __restrict__ Wskip,
                             const float* __restrict__ lnw, const float* __restrict__ lnb,
                             float* __restrict__ yout) {
    __shared__ float sWs[128 * 16];
    __shared__ float sX[16 * 132];
    int t = threadIdx.x;
    for (int i = t; i < 16 * 128; i += 256) {
        int j = i >> 7, k = i & 127;
        sWs[k * 16 + j] = Wskip[i];
    }
    int n0 = blockIdx.x * 16;
    for (int i = t; i < 16 * 128; i += 256) {
        int r = i >> 7, k = i & 127;
        sX[r * 132 + k] = x[(size_t)(n0 + r) * 128 + k];
    }
    __syncthreads();

    int warp = t >> 5, lane = t & 31;
    int nl = warp * 2 + (lane >> 4);
    int n = n0 + nl;
    int j = lane & 15;

    const float* o2 = out2 + (size_t)n * FDIM;
    float m = 0.f;
#pragma unroll
    for (int h = 0; h < HEADS; h++) m += o2[h * CH + j];
    m *= 0.125f;

    const float* xs = sX + nl * 132;
    float skip = 0.f;
#pragma unroll 8
    for (int k = 0; k < 128; k++) skip += xs[k] * sWs[k * 16 + j];

    float y = m + bias2[j] + skip;

    float sum = y;
#pragma unroll
    for (int dd = 1; dd < 16; dd <<= 1) sum += __shfl_xor_sync(0xffffffffu, sum, dd);
    float mu = sum * (1.f / 16.f);
    float diff = y - mu;
    float vs = diff * diff;
#pragma unroll
    for (int dd = 1; dd < 16; dd <<= 1) vs += __shfl_xor_sync(0xffffffffu, vs, dd);
    float var = vs * (1.f / 16.f);
    yout[(size_t)n * 16 + j] = diff * rsqrtf(var + 1e-5f) * lnw[j] + lnb[j];
}

// ---------------- launch -----------------------------------------------------
extern "C" void kernel_launch(void* const* d_in, const int* in_sizes, int n_in,
                              void* d_out, int out_size) {
    const float* x      = (const float*)d_in[0];
    const int*   ei     = (const int*)d_in[1];
    const float* Wl1    = (const float*)d_in[2];
    const float* bl1    = (const float*)d_in[3];
    const float* Wr1    = (const float*)d_in[4];
    const float* br1    = (const float*)d_in[5];
    const float* att1   = (const float*)d_in[6];
    const float* bias1  = (const float*)d_in[7];
    const float* bn_w   = (const float*)d_in[8];
    const float* bn_b   = (const float*)d_in[9];
    const float* bn_rm  = (const float*)d_in[10];
    const float* bn_rv  = (const float*)d_in[11];
    const float* Wl2    = (const float*)d_in[12];
    const float* bl2    = (const float*)d_in[13];
    const float* Wr2    = (const float*)d_in[14];
    const float* br2    = (const float*)d_in[15];
    const float* att2   = (const float*)d_in[16];
    const float* bias2  = (const float*)d_in[17];
    const float* Wskip  = (const float*)d_in[18];
    const float* ln_w   = (const float*)d_in[19];
    const float* ln_b   = (const float*)d_in[20];
    float* yout = (float*)d_out;

    float *XL, *XR, *ACC, *H;
    __nv_bfloat16 *whi, *wlo;
    cudaGetSymbolAddress((void**)&XL, g_XL);
    cudaGetSymbolAddress((void**)&XR, g_XR);
    cudaGetSymbolAddress((void**)&ACC, g_ACC);
    cudaGetSymbolAddress((void**)&H, g_H);
    cudaGetSymbolAddress((void**)&whi, g_whi);
    cudaGetSymbolAddress((void**)&wlo, g_wlo);

    cudaFuncSetAttribute(gemm_mma_kernel, cudaFuncAttributeMaxDynamicSharedMemorySize, SM_TOT);
    const int gemm_grid = (NNODE + 127) / 128;   // 391

    conv_w_kernel<<<(4 * 16384 + 255) / 256, 256>>>(Wl1, Wr1, Wl2, Wr2);
    zero_counts_kernel<<<(NNODE + 255) / 256, 256>>>();
    hist_kernel<<<(ETOT + 255) / 256, 256>>>(ei);
    scan_kernel<<<1, 1024>>>();
    fill_kernel<<<(ETOT + 255) / 256, 256>>>(ei);

    // ---- layer 1 ----
    gemm_mma_kernel<<<gemm_grid, 512, SM_TOT>>>(x, whi, wlo, bl1, br1, XL, XR, NNODE);
    gat_agg_kernel<<<(NNODE * 32 + 255) / 256, 256>>>(XL, XR, att1, ACC);
    bn_elu_kernel<<<(NNODE * FDIM + 255) / 256, 256>>>(ACC, bias1, bn_w, bn_b, bn_rm, bn_rv, H);

    // ---- layer 2 ----
    gemm_mma_kernel<<<gemm_grid, 512, SM_TOT>>>(H, whi + 32768, wlo + 32768, bl2, br2, XL, XR, NNODE);
    gat_agg_kernel<<<(NNODE * 32 + 255) / 256, 256>>>(XL, XR, att2, ACC);

    // ---- epilogue ----
    final_kernel<<<NNODE / 16, 256>>>(ACC, bias2, x, Wskip, ln_w, ln_b, yout);
}

// round 15
// speedup vs baseline: 4.6857x; 1.2154x over previous
#include <cuda_runtime.h>
#include <cuda_bf16.h>
#include <math.h>
#include <stdint.h>

#define NNODE 50000
#define NEDGE 800000
#define ETOT  (NEDGE + NNODE)
#define FDIM  128
#define HEADS 8
#define CH    16
#define NF    ((size_t)NNODE * FDIM)

#define SCAN_B   512
#define SCAN_G   ((NNODE + SCAN_B - 1) / SCAN_B)   // 98

// ---------------- static scratch --------------------------------------------
__device__ float g_XL[NNODE * FDIM];
__device__ float g_XR[NNODE * FDIM];
__device__ float g_ACC[NNODE * FDIM];
__device__ float g_H[NNODE * FDIM];
__device__ __nv_bfloat16 g_whi[4 * 16384];
__device__ __nv_bfloat16 g_wlo[4 * 16384];
__device__ int g_counts[NNODE];
__device__ int g_rowptr[NNODE + 1];
__device__ int g_wptr[NNODE];
__device__ int g_esrc[ETOT];
__device__ int g_bsum[SCAN_G];
__device__ int g_boff[SCAN_G];

__device__ __forceinline__ uint32_t smem_u32(const void* p) {
    uint32_t a;
    asm("{ .reg .u64 t; cvta.to.shared.u64 t, %1; cvt.u32.u64 %0, t; }" : "=r"(a) : "l"(p));
    return a;
}

// ---------------- CSR build --------------------------------------------------
__global__ void zero_counts_kernel() {
    int i = blockIdx.x * 256 + threadIdx.x;
    if (i < NNODE) g_counts[i] = 0;
}
__global__ void hist_kernel(const int* __restrict__ ei) {
    int e = blockIdx.x * 256 + threadIdx.x;
    if (e >= ETOT) return;
    int d = (e < NEDGE) ? ei[NEDGE + e] : (e - NEDGE);
    atomicAdd(&g_counts[d], 1);
}

// --- coalesced 3-phase exclusive scan of g_counts ---
__global__ void scan_bsum_kernel() {           // grid=SCAN_G, block=512
    int t = threadIdx.x;
    int gid = blockIdx.x * SCAN_B + t;
    int v = (gid < NNODE) ? g_counts[gid] : 0;
    __shared__ int swarp[16];
    int lane = t & 31, wid = t >> 5;
#pragma unroll
    for (int d = 16; d > 0; d >>= 1) v += __shfl_down_sync(0xffffffffu, v, d);
    if (lane == 0) swarp[wid] = v;
    __syncthreads();
    if (wid == 0) {
        int s = (lane < 16) ? swarp[lane] : 0;
#pragma unroll
        for (int d = 8; d > 0; d >>= 1) s += __shfl_down_sync(0xffffffffu, s, d);
        if (lane == 0) g_bsum[blockIdx.x] = s;
    }
}
__global__ void scan_boff_kernel() {           // 1 block, 128 threads
    int t = threadIdx.x;
    int v = (t < SCAN_G) ? g_bsum[t] : 0;
    int lane = t & 31, wid = t >> 5;
    int incl = v;
#pragma unroll
    for (int d = 1; d < 32; d <<= 1) {
        int n = __shfl_up_sync(0xffffffffu, incl, d);
        if (lane >= d) incl += n;
    }
    __shared__ int swarp[4];
    if (lane == 31) swarp[wid] = incl;
    __syncthreads();
    int woff = 0;
#pragma unroll
    for (int w = 0; w < 4; w++) if (w < wid) woff += swarp[w];
    if (t < SCAN_G) g_boff[t] = woff + incl - v;   // exclusive
}
__global__ void scan_final_kernel() {          // grid=SCAN_G, block=512
    int t = threadIdx.x;
    int gid = blockIdx.x * SCAN_B + t;
    int v = (gid < NNODE) ? g_counts[gid] : 0;
    int lane = t & 31, wid = t >> 5;
    int incl = v;
#pragma unroll
    for (int d = 1; d < 32; d <<= 1) {
        int n = __shfl_up_sync(0xffffffffu, incl, d);
        if (lane >= d) incl += n;
    }
    __shared__ int swarp[16];
    if (lane == 31) swarp[wid] = incl;
    __syncthreads();
    if (wid == 0) {
        int s = (lane < 16) ? swarp[lane] : 0;
        int si = s;
#pragma unroll
        for (int d = 1; d < 16; d <<= 1) {
            int n = __shfl_up_sync(0xffffffffu, si, d);
            if (lane >= d) si += n;
        }
        if (lane < 16) swarp[lane] = si - s;   // exclusive warp offsets
    }
    __syncthreads();
    int excl = g_boff[blockIdx.x] + swarp[wid] + incl - v;
    if (gid < NNODE) { g_rowptr[gid] = excl; g_wptr[gid] = excl; }
    if (gid == NNODE - 1) g_rowptr[NNODE] = ETOT;
}

__global__ void fill_kernel(const int* __restrict__ ei) {
    int e = blockIdx.x * 256 + threadIdx.x;
    if (e >= ETOT) return;
    int s, d;
    if (e < NEDGE) { s = ei[e]; d = ei[NEDGE + e]; }
    else { s = d = e - NEDGE; }
    int pos = atomicAdd(&g_wptr[d], 1);
    g_esrc[pos] = s;
}

// ---------------- weight hi/lo conversion ------------------------------------
__global__ void conv_w_kernel(const float* __restrict__ Wl1, const float* __restrict__ Wr1,
                              const float* __restrict__ Wl2, const float* __restrict__ Wr2) {
    int i = blockIdx.x * 256 + threadIdx.x;
    if (i >= 4 * 16384) return;
    int m = i >> 14, k = i & 16383;
    const float* src = (m == 0) ? Wl1 : (m == 1) ? Wr1 : (m == 2) ? Wl2 : Wr2;
    float v = src[k];
    __nv_bfloat16 h = __float2bfloat16_rn(v);
    g_whi[i] = h;
    g_wlo[i] = __float2bfloat16_rn(v - __bfloat162float(h));
}

// ---------------- dual GEMM via mma.sync bf16 hi/lo 3-pass -------------------
#define PAD_ROW 272
#define SM_A_HI 0
#define SM_A_LO (128 * PAD_ROW)
#define SM_B_HI (2 * 128 * PAD_ROW)
#define SM_B_LO (SM_B_HI + 256 * PAD_ROW)
#define SM_TOT  (SM_B_LO + 256 * PAD_ROW)

#define LDM4(r, addr) \
    asm volatile("ldmatrix.sync.aligned.m8n8.x4.shared.b16 {%0,%1,%2,%3}, [%4];" \
        : "=r"((r)[0]), "=r"((r)[1]), "=r"((r)[2]), "=r"((r)[3]) : "r"(addr))

#define MMA16816(c, a, b0, b1) \
    asm volatile("mma.sync.aligned.m16n8k16.row.col.f32.bf16.bf16.f32 " \
        "{%0,%1,%2,%3}, {%4,%5,%6,%7}, {%8,%9}, {%0,%1,%2,%3};" \
        : "+f"((c)[0]), "+f"((c)[1]), "+f"((c)[2]), "+f"((c)[3]) \
        : "r"((a)[0]), "r"((a)[1]), "r"((a)[2]), "r"((a)[3]), "r"(b0), "r"(b1))

__device__ __forceinline__ uint32_t pack2(float x, float y) {
    __nv_bfloat162 t;
    t.x = __float2bfloat16_rn(x);
    t.y = __float2bfloat16_rn(y);
    return *(uint32_t*)&t;
}

__global__ void __launch_bounds__(512, 1)
gemm_mma_kernel(const float* __restrict__ A,
                const __nv_bfloat16* __restrict__ Bhi,
                const __nv_bfloat16* __restrict__ Blo,
                const float* __restrict__ bl, const float* __restrict__ br,
                float* __restrict__ Yl, float* __restrict__ Yr, int M) {
    extern __shared__ char sm[];
    uint32_t sbase = smem_u32(sm);
    int tid = threadIdx.x;
    int row0 = blockIdx.x * 128;

#pragma unroll
    for (int i = 0; i < 4; i++) {
        int idx = tid + i * 512;
        int r = idx >> 4;
        int kc = idx & 15;
        int grow = row0 + r;
        float4 v0 = make_float4(0.f, 0.f, 0.f, 0.f), v1 = v0;
        if (grow < M) {
            const float4* src = (const float4*)(A + (size_t)grow * 128 + kc * 8);
            v0 = src[0]; v1 = src[1];
        }
        uint4 hi, lo;
        hi.x = pack2(v0.x, v0.y); hi.y = pack2(v0.z, v0.w);
        hi.z = pack2(v1.x, v1.y); hi.w = pack2(v1.z, v1.w);
        float h;
        h = __bfloat162float(__float2bfloat16_rn(v0.x)); float lx = v0.x - h;
        h = __bfloat162float(__float2bfloat16_rn(v0.y)); float ly = v0.y - h;
        h = __bfloat162float(__float2bfloat16_rn(v0.z)); float lz = v0.z - h;
        h = __bfloat162float(__float2bfloat16_rn(v0.w)); float lw = v0.w - h;
        lo.x = pack2(lx, ly); lo.y = pack2(lz, lw);
        h = __bfloat162float(__float2bfloat16_rn(v1.x)); lx = v1.x - h;
        h = __bfloat162float(__float2bfloat16_rn(v1.y)); ly = v1.y - h;
        h = __bfloat162float(__float2bfloat16_rn(v1.z)); lz = v1.z - h;
        h = __bfloat162float(__float2bfloat16_rn(v1.w)); lw = v1.w - h;
        lo.z = pack2(lx, ly); lo.w = pack2(lz, lw);
        uint32_t off = (uint32_t)r * PAD_ROW + (uint32_t)kc * 16;
        *(uint4*)(sm + SM_A_HI + off) = hi;
        *(uint4*)(sm + SM_A_LO + off) = lo;
    }
#pragma unroll
    for (int i = 0; i < 8; i++) {
        int idx = tid + i * 512;
        int r = idx >> 4;
        int kc = idx & 15;
        uint32_t off = (uint32_t)r * PAD_ROW + (uint32_t)kc * 16;
        *(uint4*)(sm + SM_B_HI + off) = *(const uint4*)(Bhi + (size_t)r * 128 + kc * 8);
        *(uint4*)(sm + SM_B_LO + off) = *(const uint4*)(Blo + (size_t)r * 128 + kc * 8);
    }
    __syncthreads();

    int lane = tid & 31, wid = tid >> 5;
    int warp_m = wid & 3, warp_n = wid >> 2;

    uint32_t aoff0 = (uint32_t)(warp_m * 32 + (lane & 15)) * PAD_ROW + ((lane >> 4) * 16);
    uint32_t aoff1 = aoff0 + 16 * PAD_ROW;
    uint32_t aHi0 = sbase + SM_A_HI + aoff0, aHi1 = sbase + SM_A_HI + aoff1;
    uint32_t aLo0 = sbase + SM_A_LO + aoff0, aLo1 = sbase + SM_A_LO + aoff1;
    uint32_t boff = (uint32_t)(warp_n * 64 + (lane & 7) + ((lane >> 4) & 1) * 8) * PAD_ROW
                  + (((lane >> 3) & 1) * 16);
    uint32_t bHiB = sbase + SM_B_HI + boff;
    uint32_t bLoB = sbase + SM_B_LO + boff;

    float c[2][8][4];
#pragma unroll
    for (int t = 0; t < 2; t++)
#pragma unroll
        for (int n = 0; n < 8; n++)
#pragma unroll
            for (int q = 0; q < 4; q++) c[t][n][q] = 0.f;

#pragma unroll
    for (int p = 0; p < 3; p++) {
        uint32_t ab0 = (p < 2) ? aHi0 : aLo0;
        uint32_t ab1 = (p < 2) ? aHi1 : aLo1;
        uint32_t bb  = (p == 1) ? bLoB : bHiB;
#pragma unroll
        for (int ks = 0; ks < 8; ks++) {
            uint32_t kb = ks * 32;
            uint32_t a0[4], a1[4];
            LDM4(a0, ab0 + kb);
            LDM4(a1, ab1 + kb);
#pragma unroll
            for (int g = 0; g < 4; g++) {
                uint32_t b[4];
                LDM4(b, bb + g * (16 * PAD_ROW) + kb);
                MMA16816(c[0][2 * g],     a0, b[0], b[1]);
                MMA16816(c[0][2 * g + 1], a0, b[2], b[3]);
                MMA16816(c[1][2 * g],     a1, b[0], b[1]);
                MMA16816(c[1][2 * g + 1], a1, b[2], b[3]);
            }
        }
    }

    const float* bias = (warp_n < 2) ? bl : br;
    float* Y = (warp_n < 2) ? Yl : Yr;
    int ncol0 = (warp_n & 1) * 64;
#pragma unroll
    for (int t = 0; t < 2; t++) {
        int r = row0 + warp_m * 32 + t * 16 + (lane >> 2);
#pragma unroll
        for (int nt = 0; nt < 8; nt++) {
            int col = ncol0 + nt * 8 + (lane & 3) * 2;
            float b0 = bias[col], b1 = bias[col + 1];
            if (r < M)
                *(float2*)(Y + (size_t)r * 128 + col) =
                    make_float2(c[t][nt][0] + b0, c[t][nt][1] + b1);
            if (r + 8 < M)
                *(float2*)(Y + (size_t)(r + 8) * 128 + col) =
                    make_float2(c[t][nt][2] + b0, c[t][nt][3] + b1);
        }
    }
}

// ---------------- fused GAT aggregation (one warp / dst node, 2-edge ILP) ----
__global__ void gat_agg_kernel(const float* __restrict__ xl,
                               const float* __restrict__ xr,
                               const float* __restrict__ att,
                               float* __restrict__ out) {
    int w = (blockIdx.x * blockDim.x + threadIdx.x) >> 5;
    if (w >= NNODE) return;
    int l = threadIdx.x & 31;

    const float4* xl4 = (const float4*)xl;
    float4 r = ((const float4*)xr)[(size_t)w * 32 + l];
    float4 a = ((const float4*)att)[l];

    int beg = g_rowptr[w], end = g_rowptr[w + 1];
    float4 acc = make_float4(0.f, 0.f, 0.f, 0.f);
    float den = 0.f;

    for (int base = beg; base < end; base += 32) {
        int n = end - base; if (n > 32) n = 32;
        int sid = (base + l < end) ? g_esrc[base + l] : 0;
        int j = 0;
        for (; j + 2 <= n; j += 2) {
            int s0 = __shfl_sync(0xffffffffu, sid, j);
            int s1 = __shfl_sync(0xffffffffu, sid, j + 1);
            float4 x0 = xl4[(size_t)s0 * 32 + l];
            float4 x1 = xl4[(size_t)s1 * 32 + l];
            float tx, ty, tz, tw, p0, p1;
            tx = x0.x + r.x; tx = tx > 0.f ? tx : 0.2f * tx;
            ty = x0.y + r.y; ty = ty > 0.f ? ty : 0.2f * ty;
            tz = x0.z + r.z; tz = tz > 0.f ? tz : 0.2f * tz;
            tw = x0.w + r.w; tw = tw > 0.f ? tw : 0.2f * tw;
            p0 = tx * a.x + ty * a.y + tz * a.z + tw * a.w;
            tx = x1.x + r.x; tx = tx > 0.f ? tx : 0.2f * tx;
            ty = x1.y + r.y; ty = ty > 0.f ? ty : 0.2f * ty;
            tz = x1.z + r.z; tz = tz > 0.f ? tz : 0.2f * tz;
            tw = x1.w + r.w; tw = tw > 0.f ? tw : 0.2f * tw;
            p1 = tx * a.x + ty * a.y + tz * a.z + tw * a.w;
            p0 += __shfl_xor_sync(0xffffffffu, p0, 1);
            p1 += __shfl_xor_sync(0xffffffffu, p1, 1);
            p0 += __shfl_xor_sync(0xffffffffu, p0, 2);
            p1 += __shfl_xor_sync(0xffffffffu, p1, 2);
            float e0 = __expf(p0), e1 = __expf(p1);
            den += e0 + e1;
            acc.x += e0 * x0.x + e1 * x1.x;
            acc.y += e0 * x0.y + e1 * x1.y;
            acc.z += e0 * x0.z + e1 * x1.z;
            acc.w += e0 * x0.w + e1 * x1.w;
        }
        if (j < n) {
            int s0 = __shfl_sync(0xffffffffu, sid, j);
            float4 x0 = xl4[(size_t)s0 * 32 + l];
            float tx = x0.x + r.x; tx = tx > 0.f ? tx : 0.2f * tx;
            float ty = x0.y + r.y; ty = ty > 0.f ? ty : 0.2f * ty;
            float tz = x0.z + r.z; tz = tz > 0.f ? tz : 0.2f * tz;
            float tw = x0.w + r.w; tw = tw > 0.f ? tw : 0.2f * tw;
            float p0 = tx * a.x + ty * a.y + tz * a.z + tw * a.w;
            p0 += __shfl_xor_sync(0xffffffffu, p0, 1);
            p0 += __shfl_xor_sync(0xffffffffu, p0, 2);
            float e0 = __expf(p0);
            den += e0;
            acc.x += e0 * x0.x; acc.y += e0 * x0.y;
            acc.z += e0 * x0.z; acc.w += e0 * x0.w;
        }
    }
    float inv = 1.f / den;
    ((float4*)out)[(size_t)w * 32 + l] =
        make_float4(acc.x * inv, acc.y * inv, acc.z * inv, acc.w * inv);
}

// ---------------- bias + BN(eval) + ELU --------------------------------------
__global__ void bn_elu_kernel(const float* __restrict__ acc,
                              const float* __restrict__ bias,
                              const float* __restrict__ bw, const float* __restrict__ bb,
                              const float* __restrict__ rm, const float* __restrict__ rv,
                              float* __restrict__ h1) {
    int i = blockIdx.x * 256 + threadIdx.x;
    if (i >= NNODE * FDIM) return;
    int c = i & 127;
    float v = acc[i] + bias[c];
    v = (v - rm[c]) * rsqrtf(rv[c] + 1e-5f) * bw[c] + bb[c];
    h1[i] = v > 0.f ? v : expm1f(v);
}

// ---------------- final: mean heads + bias2 + skip GEMM + LayerNorm ----------
__global__ void final_kernel(const float* __restrict__ out2,
                             const float* __restrict__ bias2,
                             const float* __restrict__ x,
                             const float* __restrict__ Wskip,
                             const float* __restrict__ lnw, const float* __restrict__ lnb,
                             float* __restrict__ yout) {
    __shared__ float sWs[128 * 16];
    __shared__ float sX[16 * 132];
    int t = threadIdx.x;
    for (int i = t; i < 16 * 128; i += 256) {
        int j = i >> 7, k = i & 127;
        sWs[k * 16 + j] = Wskip[i];
    }
    int n0 = blockIdx.x * 16;
    for (int i = t; i < 16 * 128; i += 256) {
        int r = i >> 7, k = i & 127;
        sX[r * 132 + k] = x[(size_t)(n0 + r) * 128 + k];
    }
    __syncthreads();

    int warp = t >> 5, lane = t & 31;
    int nl = warp * 2 + (lane >> 4);
    int n = n0 + nl;
    int j = lane & 15;

    const float* o2 = out2 + (size_t)n * FDIM;
    float m = 0.f;
#pragma unroll
    for (int h = 0; h < HEADS; h++) m += o2[h * CH + j];
    m *= 0.125f;

    const float* xs = sX + nl * 132;
    float skip = 0.f;
#pragma unroll 8
    for (int k = 0; k < 128; k++) skip += xs[k] * sWs[k * 16 + j];

    float y = m + bias2[j] + skip;

    float sum = y;
#pragma unroll
    for (int dd = 1; dd < 16; dd <<= 1) sum += __shfl_xor_sync(0xffffffffu, sum, dd);
    float mu = sum * (1.f / 16.f);
    float diff = y - mu;
    float vs = diff * diff;
#pragma unroll
    for (int dd = 1; dd < 16; dd <<= 1) vs += __shfl_xor_sync(0xffffffffu, vs, dd);
    float var = vs * (1.f / 16.f);
    yout[(size_t)n * 16 + j] = diff * rsqrtf(var + 1e-5f) * lnw[j] + lnb[j];
}

// ---------------- launch -----------------------------------------------------
extern "C" void kernel_launch(void* const* d_in, const int* in_sizes, int n_in,
                              void* d_out, int out_size) {
    const float* x      = (const float*)d_in[0];
    const int*   ei     = (const int*)d_in[1];
    const float* Wl1    = (const float*)d_in[2];
    const float* bl1    = (const float*)d_in[3];
    const float* Wr1    = (const float*)d_in[4];
    const float* br1    = (const float*)d_in[5];
    const float* att1   = (const float*)d_in[6];
    const float* bias1  = (const float*)d_in[7];
    const float* bn_w   = (const float*)d_in[8];
    const float* bn_b   = (const float*)d_in[9];
    const float* bn_rm  = (const float*)d_in[10];
    const float* bn_rv  = (const float*)d_in[11];
    const float* Wl2    = (const float*)d_in[12];
    const float* bl2    = (const float*)d_in[13];
    const float* Wr2    = (const float*)d_in[14];
    const float* br2    = (const float*)d_in[15];
    const float* att2   = (const float*)d_in[16];
    const float* bias2  = (const float*)d_in[17];
    const float* Wskip  = (const float*)d_in[18];
    const float* ln_w   = (const float*)d_in[19];
    const float* ln_b   = (const float*)d_in[20];
    float* yout = (float*)d_out;

    float *XL, *XR, *ACC, *H;
    __nv_bfloat16 *whi, *wlo;
    cudaGetSymbolAddress((void**)&XL, g_XL);
    cudaGetSymbolAddress((void**)&XR, g_XR);
    cudaGetSymbolAddress((void**)&ACC, g_ACC);
    cudaGetSymbolAddress((void**)&H, g_H);
    cudaGetSymbolAddress((void**)&whi, g_whi);
    cudaGetSymbolAddress((void**)&wlo, g_wlo);

    cudaFuncSetAttribute(gemm_mma_kernel, cudaFuncAttributeMaxDynamicSharedMemorySize, SM_TOT);
    const int gemm_grid = (NNODE + 127) / 128;

    conv_w_kernel<<<(4 * 16384 + 255) / 256, 256>>>(Wl1, Wr1, Wl2, Wr2);
    zero_counts_kernel<<<(NNODE + 255) / 256, 256>>>();
    hist_kernel<<<(ETOT + 255) / 256, 256>>>(ei);
    scan_bsum_kernel<<<SCAN_G, SCAN_B>>>();
    scan_boff_kernel<<<1, 128>>>();
    scan_final_kernel<<<SCAN_G, SCAN_B>>>();
    fill_kernel<<<(ETOT + 255) / 256, 256>>>(ei);

    // ---- layer 1 ----
    gemm_mma_kernel<<<gemm_grid, 512, SM_TOT>>>(x, whi, wlo, bl1, br1, XL, XR, NNODE);
    gat_agg_kernel<<<(NNODE * 32 + 255) / 256, 256>>>(XL, XR, att1, ACC);
    bn_elu_kernel<<<(NNODE * FDIM + 255) / 256, 256>>>(ACC, bias1, bn_w, bn_b, bn_rm, bn_rv, H);

    // ---- layer 2 ----
    gemm_mma_kernel<<<gemm_grid, 512, SM_TOT>>>(H, whi + 32768, wlo + 32768, bl2, br2, XL, XR, NNODE);
    gat_agg_kernel<<<(NNODE * 32 + 255) / 256, 256>>>(XL, XR, att2, ACC);

    // ---- epilogue ----
    final_kernel<<<NNODE / 16, 256>>>(ACC, bias2, x, Wskip, ln_w, ln_b, yout);
}

// round 16
// speedup vs baseline: 4.8509x; 1.0353x over previous
#include <cuda_runtime.h>
#include <cuda_bf16.h>
#include <math.h>
#include <stdint.h>

#define NNODE 50000
#define NEDGE 800000
#define ETOT  (NEDGE + NNODE)
#define FDIM  128
#define HEADS 8
#define CH    16
#define NF    ((size_t)NNODE * FDIM)

#define CSR_B 512
#define CSR_G 98                        // 98*512 = 50176 >= NNODE; all-resident on 148 SMs

// ---------------- static scratch --------------------------------------------
__device__ float g_XL[NNODE * FDIM];
__device__ float g_XR[NNODE * FDIM];
__device__ float g_ACC[NNODE * FDIM];
__device__ float g_H[NNODE * FDIM];
__device__ __nv_bfloat16 g_whi[4 * 16384];
__device__ __nv_bfloat16 g_wlo[4 * 16384];
__device__ float g_bnA[FDIM];
__device__ float g_bnB[FDIM];
__device__ int g_counts[NNODE];
__device__ int g_rowptr[NNODE + 1];
__device__ int g_wptr[NNODE];
__device__ int g_esrc[ETOT];
__device__ int g_bsum[CSR_G];
__device__ int g_sync0, g_sync1, g_sync2;

__device__ __forceinline__ uint32_t smem_u32(const void* p) {
    uint32_t a;
    asm("{ .reg .u64 t; cvta.to.shared.u64 t, %1; cvt.u32.u64 %0, t; }" : "=r"(a) : "l"(p));
    return a;
}

// ---------------- setup: W hi/lo + zero counts + BN coeffs + sync reset ------
__global__ void setup_kernel(const float* __restrict__ Wl1, const float* __restrict__ Wr1,
                             const float* __restrict__ Wl2, const float* __restrict__ Wr2,
                             const float* __restrict__ bias1,
                             const float* __restrict__ bw, const float* __restrict__ bb,
                             const float* __restrict__ rm, const float* __restrict__ rv) {
    int i = blockIdx.x * 256 + threadIdx.x;
    if (i < 4 * 16384) {
        int m = i >> 14, k = i & 16383;
        const float* src = (m == 0) ? Wl1 : (m == 1) ? Wr1 : (m == 2) ? Wl2 : Wr2;
        float v = src[k];
        __nv_bfloat16 h = __float2bfloat16_rn(v);
        g_whi[i] = h;
        g_wlo[i] = __float2bfloat16_rn(v - __bfloat162float(h));
    }
    if (i < NNODE) g_counts[i] = 0;
    if (i < FDIM) {
        float A = bw[i] * rsqrtf(rv[i] + 1e-5f);
        g_bnA[i] = A;
        g_bnB[i] = (bias1[i] - rm[i]) * A + bb[i];
    }
    if (i == 0) { g_sync0 = 0; g_sync1 = 0; g_sync2 = 0; }
}

// ---------------- one-kernel CSR build: hist -> scan -> fill ------------------
__device__ __forceinline__ void grid_barrier(int* cnt) {
    __syncthreads();
    if (threadIdx.x == 0) {
        __threadfence();
        atomicAdd(cnt, 1);
        while (atomicAdd(cnt, 0) < CSR_G) { }
    }
    __syncthreads();
}

__global__ void __launch_bounds__(CSR_B, 1)
csr_mega_kernel(const int* __restrict__ ei) {
    const int t = threadIdx.x, b = blockIdx.x;
    const int nth = CSR_B * CSR_G;
    const int tidg = b * CSR_B + t;
    const int lane = t & 31, wid = t >> 5;
    __shared__ int swarp[16];
    __shared__ int s_bcast;

    // ---- phase 0: histogram ----
    for (int e = tidg; e < ETOT; e += nth) {
        int d = (e < NEDGE) ? ei[NEDGE + e] : (e - NEDGE);
        atomicAdd(&g_counts[d], 1);
    }
    grid_barrier(&g_sync0);

    // ---- phase 1: block scan + block total ----
    int v = (tidg < NNODE) ? g_counts[tidg] : 0;
    int incl = v;
#pragma unroll
    for (int d = 1; d < 32; d <<= 1) {
        int n = __shfl_up_sync(0xffffffffu, incl, d);
        if (lane >= d) incl += n;
    }
    if (lane == 31) swarp[wid] = incl;
    __syncthreads();
    if (wid == 0) {
        int s = (lane < 16) ? swarp[lane] : 0;
        int si = s;
#pragma unroll
        for (int d = 1; d < 16; d <<= 1) {
            int n = __shfl_up_sync(0xffffffffu, si, d);
            if (lane >= d) si += n;
        }
        if (lane < 16) swarp[lane] = si - s;         // exclusive warp offsets
        if (lane == 15) g_bsum[b] = si;              // block total
    }
    __syncthreads();
    int excl_in_block = swarp[wid] + incl - v;

    grid_barrier(&g_sync1);                          // all g_bsum visible

    // ---- cross-block exclusive prefix: sum of g_bsum[0..b-1] ----
    {
        int pv = (t < b) ? __ldcg(&g_bsum[t]) : 0;   // b <= 97 < 512
#pragma unroll
        for (int d = 16; d > 0; d >>= 1) pv += __shfl_down_sync(0xffffffffu, pv, d);
        __syncthreads();                             // swarp reuse safe
        if (lane == 0) swarp[wid] = pv;
        __syncthreads();
        if (t == 0) {
            int s = 0;
#pragma unroll
            for (int w = 0; w < 16; w++) s += swarp[w];
            s_bcast = s;
        }
        __syncthreads();
    }
    int excl = s_bcast + excl_in_block;
    if (tidg < NNODE) { g_rowptr[tidg] = excl; g_wptr[tidg] = excl; }
    if (tidg == NNODE - 1) g_rowptr[NNODE] = ETOT;

    grid_barrier(&g_sync2);                          // all wptr written

    // ---- phase 2: fill ----
    for (int e = tidg; e < ETOT; e += nth) {
        int s, d;
        if (e < NEDGE) { s = ei[e]; d = ei[NEDGE + e]; }
        else { s = d = e - NEDGE; }
        int pos = atomicAdd(&g_wptr[d], 1);
        g_esrc[pos] = s;
    }
}

// ---------------- dual GEMM via mma.sync bf16 hi/lo 3-pass -------------------
#define PAD_ROW 272
#define SM_A_HI 0
#define SM_A_LO (128 * PAD_ROW)
#define SM_B_HI (2 * 128 * PAD_ROW)
#define SM_B_LO (SM_B_HI + 256 * PAD_ROW)
#define SM_TOT  (SM_B_LO + 256 * PAD_ROW)

#define LDM4(r, addr) \
    asm volatile("ldmatrix.sync.aligned.m8n8.x4.shared.b16 {%0,%1,%2,%3}, [%4];" \
        : "=r"((r)[0]), "=r"((r)[1]), "=r"((r)[2]), "=r"((r)[3]) : "r"(addr))

#define MMA16816(c, a, b0, b1) \
    asm volatile("mma.sync.aligned.m16n8k16.row.col.f32.bf16.bf16.f32 " \
        "{%0,%1,%2,%3}, {%4,%5,%6,%7}, {%8,%9}, {%0,%1,%2,%3};" \
        : "+f"((c)[0]), "+f"((c)[1]), "+f"((c)[2]), "+f"((c)[3]) \
        : "r"((a)[0]), "r"((a)[1]), "r"((a)[2]), "r"((a)[3]), "r"(b0), "r"(b1))

__device__ __forceinline__ uint32_t pack2(float x, float y) {
    __nv_bfloat162 t;
    t.x = __float2bfloat16_rn(x);
    t.y = __float2bfloat16_rn(y);
    return *(uint32_t*)&t;
}

__global__ void __launch_bounds__(512, 1)
gemm_mma_kernel(const float* __restrict__ A,
                const __nv_bfloat16* __restrict__ Bhi,
                const __nv_bfloat16* __restrict__ Blo,
                const float* __restrict__ bl, const float* __restrict__ br,
                float* __restrict__ Yl, float* __restrict__ Yr, int M) {
    extern __shared__ char sm[];
    uint32_t sbase = smem_u32(sm);
    int tid = threadIdx.x;
    int row0 = blockIdx.x * 128;

#pragma unroll
    for (int i = 0; i < 4; i++) {
        int idx = tid + i * 512;
        int r = idx >> 4;
        int kc = idx & 15;
        int grow = row0 + r;
        float4 v0 = make_float4(0.f, 0.f, 0.f, 0.f), v1 = v0;
        if (grow < M) {
            const float4* src = (const float4*)(A + (size_t)grow * 128 + kc * 8);
            v0 = src[0]; v1 = src[1];
        }
        uint4 hi, lo;
        hi.x = pack2(v0.x, v0.y); hi.y = pack2(v0.z, v0.w);
        hi.z = pack2(v1.x, v1.y); hi.w = pack2(v1.z, v1.w);
        float h;
        h = __bfloat162float(__float2bfloat16_rn(v0.x)); float lx = v0.x - h;
        h = __bfloat162float(__float2bfloat16_rn(v0.y)); float ly = v0.y - h;
        h = __bfloat162float(__float2bfloat16_rn(v0.z)); float lz = v0.z - h;
        h = __bfloat162float(__float2bfloat16_rn(v0.w)); float lw = v0.w - h;
        lo.x = pack2(lx, ly); lo.y = pack2(lz, lw);
        h = __bfloat162float(__float2bfloat16_rn(v1.x)); lx = v1.x - h;
        h = __bfloat162float(__float2bfloat16_rn(v1.y)); ly = v1.y - h;
        h = __bfloat162float(__float2bfloat16_rn(v1.z)); lz = v1.z - h;
        h = __bfloat162float(__float2bfloat16_rn(v1.w)); lw = v1.w - h;
        lo.z = pack2(lx, ly); lo.w = pack2(lz, lw);
        uint32_t off = (uint32_t)r * PAD_ROW + (uint32_t)kc * 16;
        *(uint4*)(sm + SM_A_HI + off) = hi;
        *(uint4*)(sm + SM_A_LO + off) = lo;
    }
#pragma unroll
    for (int i = 0; i < 8; i++) {
        int idx = tid + i * 512;
        int r = idx >> 4;
        int kc = idx & 15;
        uint32_t off = (uint32_t)r * PAD_ROW + (uint32_t)kc * 16;
        *(uint4*)(sm + SM_B_HI + off) = *(const uint4*)(Bhi + (size_t)r * 128 + kc * 8);
        *(uint4*)(sm + SM_B_LO + off) = *(const uint4*)(Blo + (size_t)r * 128 + kc * 8);
    }
    __syncthreads();

    int lane = tid & 31, wid = tid >> 5;
    int warp_m = wid & 3, warp_n = wid >> 2;

    uint32_t aoff0 = (uint32_t)(warp_m * 32 + (lane & 15)) * PAD_ROW + ((lane >> 4) * 16);
    uint32_t aoff1 = aoff0 + 16 * PAD_ROW;
    uint32_t aHi0 = sbase + SM_A_HI + aoff0, aHi1 = sbase + SM_A_HI + aoff1;
    uint32_t aLo0 = sbase + SM_A_LO + aoff0, aLo1 = sbase + SM_A_LO + aoff1;
    uint32_t boff = (uint32_t)(warp_n * 64 + (lane & 7) + ((lane >> 4) & 1) * 8) * PAD_ROW
                  + (((lane >> 3) & 1) * 16);
    uint32_t bHiB = sbase + SM_B_HI + boff;
    uint32_t bLoB = sbase + SM_B_LO + boff;

    float c[2][8][4];
#pragma unroll
    for (int t = 0; t < 2; t++)
#pragma unroll
        for (int n = 0; n < 8; n++)
#pragma unroll
            for (int q = 0; q < 4; q++) c[t][n][q] = 0.f;

#pragma unroll
    for (int p = 0; p < 3; p++) {
        uint32_t ab0 = (p < 2) ? aHi0 : aLo0;
        uint32_t ab1 = (p < 2) ? aHi1 : aLo1;
        uint32_t bb  = (p == 1) ? bLoB : bHiB;
#pragma unroll
        for (int ks = 0; ks < 8; ks++) {
            uint32_t kb = ks * 32;
            uint32_t a0[4], a1[4];
            LDM4(a0, ab0 + kb);
            LDM4(a1, ab1 + kb);
#pragma unroll
            for (int g = 0; g < 4; g++) {
                uint32_t b[4];
                LDM4(b, bb + g * (16 * PAD_ROW) + kb);
                MMA16816(c[0][2 * g],     a0, b[0], b[1]);
                MMA16816(c[0][2 * g + 1], a0, b[2], b[3]);
                MMA16816(c[1][2 * g],     a1, b[0], b[1]);
                MMA16816(c[1][2 * g + 1], a1, b[2], b[3]);
            }
        }
    }

    const float* bias = (warp_n < 2) ? bl : br;
    float* Y = (warp_n < 2) ? Yl : Yr;
    int ncol0 = (warp_n & 1) * 64;
#pragma unroll
    for (int t = 0; t < 2; t++) {
        int r = row0 + warp_m * 32 + t * 16 + (lane >> 2);
#pragma unroll
        for (int nt = 0; nt < 8; nt++) {
            int col = ncol0 + nt * 8 + (lane & 3) * 2;
            float b0 = bias[col], b1 = bias[col + 1];
            if (r < M)
                *(float2*)(Y + (size_t)r * 128 + col) =
                    make_float2(c[t][nt][0] + b0, c[t][nt][1] + b1);
            if (r + 8 < M)
                *(float2*)(Y + (size_t)(r + 8) * 128 + col) =
                    make_float2(c[t][nt][2] + b0, c[t][nt][3] + b1);
        }
    }
}

// ---------------- fused GAT aggregation (+ optional BN/ELU epilogue) ---------
__global__ void gat_agg_kernel(const float* __restrict__ xl,
                               const float* __restrict__ xr,
                               const float* __restrict__ att,
                               float* __restrict__ out, int fuse_bn) {
    int w = (blockIdx.x * blockDim.x + threadIdx.x) >> 5;
    if (w >= NNODE) return;
    int l = threadIdx.x & 31;

    const float4* xl4 = (const float4*)xl;
    float4 r = ((const float4*)xr)[(size_t)w * 32 + l];
    float4 a = ((const float4*)att)[l];

    int beg = g_rowptr[w], end = g_rowptr[w + 1];
    float4 acc = make_float4(0.f, 0.f, 0.f, 0.f);
    float den = 0.f;

    for (int base = beg; base < end; base += 32) {
        int n = end - base; if (n > 32) n = 32;
        int sid = (base + l < end) ? g_esrc[base + l] : 0;
        int j = 0;
        for (; j + 2 <= n; j += 2) {
            int s0 = __shfl_sync(0xffffffffu, sid, j);
            int s1 = __shfl_sync(0xffffffffu, sid, j + 1);
            float4 x0 = xl4[(size_t)s0 * 32 + l];
            float4 x1 = xl4[(size_t)s1 * 32 + l];
            float tx, ty, tz, tw, p0, p1;
            tx = x0.x + r.x; tx = tx > 0.f ? tx : 0.2f * tx;
            ty = x0.y + r.y; ty = ty > 0.f ? ty : 0.2f * ty;
            tz = x0.z + r.z; tz = tz > 0.f ? tz : 0.2f * tz;
            tw = x0.w + r.w; tw = tw > 0.f ? tw : 0.2f * tw;
            p0 = tx * a.x + ty * a.y + tz * a.z + tw * a.w;
            tx = x1.x + r.x; tx = tx > 0.f ? tx : 0.2f * tx;
            ty = x1.y + r.y; ty = ty > 0.f ? ty : 0.2f * ty;
            tz = x1.z + r.z; tz = tz > 0.f ? tz : 0.2f * tz;
            tw = x1.w + r.w; tw = tw > 0.f ? tw : 0.2f * tw;
            p1 = tx * a.x + ty * a.y + tz * a.z + tw * a.w;
            p0 += __shfl_xor_sync(0xffffffffu, p0, 1);
            p1 += __shfl_xor_sync(0xffffffffu, p1, 1);
            p0 += __shfl_xor_sync(0xffffffffu, p0, 2);
            p1 += __shfl_xor_sync(0xffffffffu, p1, 2);
            float e0 = __expf(p0), e1 = __expf(p1);
            den += e0 + e1;
            acc.x += e0 * x0.x + e1 * x1.x;
            acc.y += e0 * x0.y + e1 * x1.y;
            acc.z += e0 * x0.z + e1 * x1.z;
            acc.w += e0 * x0.w + e1 * x1.w;
        }
        if (j < n) {
            int s0 = __shfl_sync(0xffffffffu, sid, j);
            float4 x0 = xl4[(size_t)s0 * 32 + l];
            float tx = x0.x + r.x; tx = tx > 0.f ? tx : 0.2f * tx;
            float ty = x0.y + r.y; ty = ty > 0.f ? ty : 0.2f * ty;
            float tz = x0.z + r.z; tz = tz > 0.f ? tz : 0.2f * tz;
            float tw = x0.w + r.w; tw = tw > 0.f ? tw : 0.2f * tw;
            float p0 = tx * a.x + ty * a.y + tz * a.z + tw * a.w;
            p0 += __shfl_xor_sync(0xffffffffu, p0, 1);
            p0 += __shfl_xor_sync(0xffffffffu, p0, 2);
            float e0 = __expf(p0);
            den += e0;
            acc.x += e0 * x0.x; acc.y += e0 * x0.y;
            acc.z += e0 * x0.z; acc.w += e0 * x0.w;
        }
    }
    float inv = 1.f / den;
    float4 v = make_float4(acc.x * inv, acc.y * inv, acc.z * inv, acc.w * inv);
    if (fuse_bn) {
        // v' = elu(v*A + B), per channel c = 4l..4l+3
        float4 A = ((const float4*)g_bnA)[l];
        float4 B = ((const float4*)g_bnB)[l];
        v.x = v.x * A.x + B.x; v.x = v.x > 0.f ? v.x : expm1f(v.x);
        v.y = v.y * A.y + B.y; v.y = v.y > 0.f ? v.y : expm1f(v.y);
        v.z = v.z * A.z + B.z; v.z = v.z > 0.f ? v.z : expm1f(v.z);
        v.w = v.w * A.w + B.w; v.w = v.w > 0.f ? v.w : expm1f(v.w);
    }
    ((float4*)out)[(size_t)w * 32 + l] = v;
}

// ---------------- final: mean heads + bias2 + skip GEMM + LayerNorm ----------
__global__ void final_kernel(const float* __restrict__ out2,
                             const float* __restrict__ bias2,
                             const float* __restrict__ x,
                             const float* __restrict__ Wskip,
                             const float* __restrict__ lnw, const float* __restrict__ lnb,
                             float* __restrict__ yout) {
    __shared__ float sWs[128 * 16];
    __shared__ float sX[16 * 132];
    int t = threadIdx.x;
    for (int i = t; i < 16 * 128; i += 256) {
        int j = i >> 7, k = i & 127;
        sWs[k * 16 + j] = Wskip[i];
    }
    int n0 = blockIdx.x * 16;
    for (int i = t; i < 16 * 128; i += 256) {
        int r = i >> 7, k = i & 127;
        sX[r * 132 + k] = x[(size_t)(n0 + r) * 128 + k];
    }
    __syncthreads();

    int warp = t >> 5, lane = t & 31;
    int nl = warp * 2 + (lane >> 4);
    int n = n0 + nl;
    int j = lane & 15;

    const float* o2 = out2 + (size_t)n * FDIM;
    float m = 0.f;
#pragma unroll
    for (int h = 0; h < HEADS; h++) m += o2[h * CH + j];
    m *= 0.125f;

    const float* xs = sX + nl * 132;
    float skip = 0.f;
#pragma unroll 8
    for (int k = 0; k < 128; k++) skip += xs[k] * sWs[k * 16 + j];

    float y = m + bias2[j] + skip;

    float sum = y;
#pragma unroll
    for (int dd = 1; dd < 16; dd <<= 1) sum += __shfl_xor_sync(0xffffffffu, sum, dd);
    float mu = sum * (1.f / 16.f);
    float diff = y - mu;
    float vs = diff * diff;
#pragma unroll
    for (int dd = 1; dd < 16; dd <<= 1) vs += __shfl_xor_sync(0xffffffffu, vs, dd);
    float var = vs * (1.f / 16.f);
    yout[(size_t)n * 16 + j] = diff * rsqrtf(var + 1e-5f) * lnw[j] + lnb[j];
}

// ---------------- launch -----------------------------------------------------
extern "C" void kernel_launch(void* const* d_in, const int* in_sizes, int n_in,
                              void* d_out, int out_size) {
    const float* x      = (const float*)d_in[0];
    const int*   ei     = (const int*)d_in[1];
    const float* Wl1    = (const float*)d_in[2];
    const float* bl1    = (const float*)d_in[3];
    const float* Wr1    = (const float*)d_in[4];
    const float* br1    = (const float*)d_in[5];
    const float* att1   = (const float*)d_in[6];
    const float* bias1  = (const float*)d_in[7];
    const float* bn_w   = (const float*)d_in[8];
    const float* bn_b   = (const float*)d_in[9];
    const float* bn_rm  = (const float*)d_in[10];
    const float* bn_rv  = (const float*)d_in[11];
    const float* Wl2    = (const float*)d_in[12];
    const float* bl2    = (const float*)d_in[13];
    const float* Wr2    = (const float*)d_in[14];
    const float* br2    = (const float*)d_in[15];
    const float* att2   = (const float*)d_in[16];
    const float* bias2  = (const float*)d_in[17];
    const float* Wskip  = (const float*)d_in[18];
    const float* ln_w   = (const float*)d_in[19];
    const float* ln_b   = (const float*)d_in[20];
    float* yout = (float*)d_out;

    float *XL, *XR, *ACC, *H;
    __nv_bfloat16 *whi, *wlo;
    cudaGetSymbolAddress((void**)&XL, g_XL);
    cudaGetSymbolAddress((void**)&XR, g_XR);
    cudaGetSymbolAddress((void**)&ACC, g_ACC);
    cudaGetSymbolAddress((void**)&H, g_H);
    cudaGetSymbolAddress((void**)&whi, g_whi);
    cudaGetSymbolAddress((void**)&wlo, g_wlo);

    cudaFuncSetAttribute(gemm_mma_kernel, cudaFuncAttributeMaxDynamicSharedMemorySize, SM_TOT);
    const int gemm_grid = (NNODE + 127) / 128;

    // 1. setup: W conversion + zero counts + BN coeffs + sync reset
    setup_kernel<<<(4 * 16384 + 255) / 256, 256>>>(Wl1, Wr1, Wl2, Wr2,
                                                   bias1, bn_w, bn_b, bn_rm, bn_rv);
    // 2. CSR build in one kernel (hist -> scan -> fill, grid barriers)
    csr_mega_kernel<<<CSR_G, CSR_B>>>(ei);

    // 3-4. layer 1
    gemm_mma_kernel<<<gemm_grid, 512, SM_TOT>>>(x, whi, wlo, bl1, br1, XL, XR, NNODE);
    gat_agg_kernel<<<(NNODE * 32 + 255) / 256, 256>>>(XL, XR, att1, H, 1);

    // 5-6. layer 2
    gemm_mma_kernel<<<gemm_grid, 512, SM_TOT>>>(H, whi + 32768, wlo + 32768, bl2, br2, XL, XR, NNODE);
    gat_agg_kernel<<<(NNODE * 32 + 255) / 256, 256>>>(XL, XR, att2, ACC, 0);

    // 7. epilogue
    final_kernel<<<NNODE / 16, 256>>>(ACC, bias2, x, Wskip, ln_w, ln_b, yout);
}